// round 3
// baseline (speedup 1.0000x reference)
#include <cuda_runtime.h>

#define NN 100000
#define NE 1600000
#define NG 256

// Scratch (static __device__ arrays; no allocation anywhere)
__device__ float g_bufA[NN * 64];
__device__ float g_bufB[NN * 64];
__device__ float g_tbuf[NN * 16];
__device__ float g_accum[NN * 32];
__device__ float g_cnt[NN];
__device__ float g_pool[NG * 2];
__device__ float g_gcnt[NG];

__global__ void k_zero_misc() {
    int i = blockIdx.x * blockDim.x + threadIdx.x;
    if (i < NN) g_cnt[i] = 0.f;
    if (i < NG * 2) g_pool[i] = 0.f;
    if (i < NG) g_gcnt[i] = 0.f;
}

__global__ void k_zero_accum(int n) {
    int i = blockIdx.x * blockDim.x + threadIdx.x;
    if (i < n) g_accum[i] = 0.f;
}

__global__ void k_count(const int* __restrict__ dst) {
    int e = blockIdx.x * blockDim.x + threadIdx.x;
    if (e < NE) atomicAdd(&g_cnt[dst[e]], 1.f);
}

// t[i,:] = h[i,:] @ W  (DIN x DOUT)
template <int DIN, int DOUT>
__global__ void k_transform(const float* __restrict__ h,
                            const float* __restrict__ W,
                            float* __restrict__ t) {
    __shared__ float sW[DIN * DOUT];
    for (int idx = threadIdx.x; idx < DIN * DOUT; idx += blockDim.x) sW[idx] = W[idx];
    __syncthreads();
    int i = blockIdx.x * blockDim.x + threadIdx.x;
    if (i >= NN) return;
    float acc[DOUT];
#pragma unroll
    for (int j = 0; j < DOUT; j++) acc[j] = 0.f;
#pragma unroll 2
    for (int k = 0; k < DIN; k++) {
        float hv = h[(size_t)i * DIN + k];
#pragma unroll
        for (int j = 0; j < DOUT; j++) acc[j] += hv * sW[k * DOUT + j];
    }
#pragma unroll
    for (int j = 0; j < DOUT; j++) t[(size_t)i * DOUT + j] = acc[j];
}

// scatter-add t[src,:] into g_accum[dst,:], width W (W divisible by 4)
template <int W>
__global__ void k_scatter(const float* __restrict__ t,
                          const int* __restrict__ src,
                          const int* __restrict__ dst) {
    constexpr int C = W / 4;
    int idx = blockIdx.x * blockDim.x + threadIdx.x;
    if (idx >= NE * C) return;
    int e = idx / C;
    int c = idx - e * C;
    int s = src[e], d = dst[e];
    const float4 v = *reinterpret_cast<const float4*>(t + (size_t)s * W + c * 4);
    float* a = g_accum + (size_t)d * W + c * 4;
    atomicAdd(a + 0, v.x);
    atomicAdd(a + 1, v.y);
    atomicAdd(a + 2, v.z);
    atomicAdd(a + 3, v.w);
}

__global__ void k_scatter2(const float* __restrict__ t,
                           const int* __restrict__ src,
                           const int* __restrict__ dst) {
    int e = blockIdx.x * blockDim.x + threadIdx.x;
    if (e >= NE) return;
    int s = src[e], d = dst[e];
    const float2 v = *reinterpret_cast<const float2*>(t + (size_t)s * 2);
    atomicAdd(&g_accum[(size_t)d * 2 + 0], v.x);
    atomicAdd(&g_accum[(size_t)d * 2 + 1], v.y);
}

// post-transform layer: out = relu((accum/cnt) @ Wl + bl + h @ Wr)
// accum has width DIN.
template <int DIN, int DOUT>
__global__ void k_update_post(const float* __restrict__ h,
                              const float* __restrict__ Wl,
                              const float* __restrict__ bl,
                              const float* __restrict__ Wr,
                              float* __restrict__ out) {
    __shared__ float sWl[DIN * DOUT];
    __shared__ float sWr[DIN * DOUT];
    __shared__ float sb[DOUT];
    for (int idx = threadIdx.x; idx < DIN * DOUT; idx += blockDim.x) {
        sWl[idx] = Wl[idx];
        sWr[idx] = Wr[idx];
    }
    for (int idx = threadIdx.x; idx < DOUT; idx += blockDim.x) sb[idx] = bl[idx];
    __syncthreads();
    int i = blockIdx.x * blockDim.x + threadIdx.x;
    if (i >= NN) return;
    float inv = 1.f / fmaxf(g_cnt[i], 1.f);
    float acc[DOUT];
#pragma unroll
    for (int j = 0; j < DOUT; j++) acc[j] = sb[j];
#pragma unroll 2
    for (int k = 0; k < DIN; k++) {
        float a = g_accum[(size_t)i * DIN + k] * inv;
        float hv = h[(size_t)i * DIN + k];
#pragma unroll
        for (int j = 0; j < DOUT; j++) {
            acc[j] += a * sWl[k * DOUT + j];
            acc[j] += hv * sWr[k * DOUT + j];
        }
    }
#pragma unroll
    for (int j = 0; j < DOUT; j++) out[(size_t)i * DOUT + j] = fmaxf(acc[j], 0.f);
}

// pre-transform layer: out = relu(accum/cnt + bl + h @ Wr)
// accum has width DOUT (already transformed by Wl before scatter).
template <int DIN, int DOUT>
__global__ void k_update_pre(const float* __restrict__ h,
                             const float* __restrict__ bl,
                             const float* __restrict__ Wr,
                             float* __restrict__ out) {
    __shared__ float sWr[DIN * DOUT];
    __shared__ float sb[DOUT];
    for (int idx = threadIdx.x; idx < DIN * DOUT; idx += blockDim.x) sWr[idx] = Wr[idx];
    for (int idx = threadIdx.x; idx < DOUT; idx += blockDim.x) sb[idx] = bl[idx];
    __syncthreads();
    int i = blockIdx.x * blockDim.x + threadIdx.x;
    if (i >= NN) return;
    float inv = 1.f / fmaxf(g_cnt[i], 1.f);
    float acc[DOUT];
#pragma unroll
    for (int j = 0; j < DOUT; j++) acc[j] = g_accum[(size_t)i * DOUT + j] * inv + sb[j];
#pragma unroll 2
    for (int k = 0; k < DIN; k++) {
        float hv = h[(size_t)i * DIN + k];
#pragma unroll
        for (int j = 0; j < DOUT; j++) acc[j] += hv * sWr[k * DOUT + j];
    }
#pragma unroll
    for (int j = 0; j < DOUT; j++) out[(size_t)i * DOUT + j] = fmaxf(acc[j], 0.f);
}

__global__ void k_pool(const float* __restrict__ h, const int* __restrict__ batch) {
    int i = blockIdx.x * blockDim.x + threadIdx.x;
    if (i >= NN) return;
    int g = batch[i];
    atomicAdd(&g_pool[2 * g + 0], h[(size_t)2 * i + 0]);
    atomicAdd(&g_pool[2 * g + 1], h[(size_t)2 * i + 1]);
    atomicAdd(&g_gcnt[g], 1.f);
}

__global__ void k_softmax(float* __restrict__ out) {
    int g = blockIdx.x * blockDim.x + threadIdx.x;
    if (g >= NG) return;
    float c = fmaxf(g_gcnt[g], 1.f);
    float a = g_pool[2 * g + 0] / c;
    float b = g_pool[2 * g + 1] / c;
    float m = fmaxf(a, b);
    float ea = expf(a - m);
    float eb = expf(b - m);
    float s = ea + eb;
    out[2 * g + 0] = ea / s;
    out[2 * g + 1] = eb / s;
}

extern "C" void kernel_launch(void* const* d_in, const int* in_sizes, int n_in,
                              void* d_out, int out_size) {
    const float* x = (const float*)d_in[0];
    const int* ei = (const int*)d_in[1];
    const int* batch = (const int*)d_in[2];
    const float* Wl0 = (const float*)d_in[3];
    const float* bl0 = (const float*)d_in[4];
    const float* Wr0 = (const float*)d_in[5];
    const float* Wl1 = (const float*)d_in[6];
    const float* bl1 = (const float*)d_in[7];
    const float* Wr1 = (const float*)d_in[8];
    const float* Wl2 = (const float*)d_in[9];
    const float* bl2 = (const float*)d_in[10];
    const float* Wr2 = (const float*)d_in[11];
    const float* Wl3 = (const float*)d_in[12];
    const float* bl3 = (const float*)d_in[13];
    const float* Wr3 = (const float*)d_in[14];
    float* out = (float*)d_out;

    const int* src = ei;
    const int* dst = ei + NE;

    float *bufA, *bufB, *tbuf;
    cudaGetSymbolAddress((void**)&bufA, g_bufA);
    cudaGetSymbolAddress((void**)&bufB, g_bufB);
    cudaGetSymbolAddress((void**)&tbuf, g_tbuf);

    const int TB = 256;
    auto nb = [](long n, int tb) { return (int)((n + tb - 1) / tb); };

    k_zero_misc<<<nb(NN, TB), TB>>>();
    k_count<<<nb(NE, TB), TB>>>(dst);

    // L0: 56 -> 16 (pre-transform, scatter width 16)
    k_transform<56, 16><<<nb(NN, 128), 128>>>(x, Wl0, tbuf);
    k_zero_accum<<<nb((long)NN * 16, TB), TB>>>(NN * 16);
    k_scatter<16><<<nb((long)NE * 4, TB), TB>>>(tbuf, src, dst);
    k_update_pre<56, 16><<<nb(NN, 128), 128>>>(x, bl0, Wr0, bufA);

    // L1: 16 -> 32 (post-transform, scatter width 16)
    k_zero_accum<<<nb((long)NN * 16, TB), TB>>>(NN * 16);
    k_scatter<16><<<nb((long)NE * 4, TB), TB>>>(bufA, src, dst);
    k_update_post<16, 32><<<nb(NN, 128), 128>>>(bufA, Wl1, bl1, Wr1, bufB);

    // L2: 32 -> 64 (post-transform, scatter width 32)
    k_zero_accum<<<nb((long)NN * 32, TB), TB>>>(NN * 32);
    k_scatter<32><<<nb((long)NE * 8, TB), TB>>>(bufB, src, dst);
    k_update_post<32, 64><<<nb(NN, 128), 128>>>(bufB, Wl2, bl2, Wr2, bufA);

    // L3: 64 -> 2 (pre-transform, scatter width 2)
    k_transform<64, 2><<<nb(NN, 128), 128>>>(bufA, Wl3, tbuf);
    k_zero_accum<<<nb((long)NN * 2, TB), TB>>>(NN * 2);
    k_scatter2<<<nb(NE, TB), TB>>>(tbuf, src, dst);
    k_update_pre<64, 2><<<nb(NN, 128), 128>>>(bufA, bl3, Wr3, bufB);

    // global mean pool + softmax
    k_pool<<<nb(NN, TB), TB>>>(bufB, batch);
    k_softmax<<<1, 256>>>(out);
}

// round 5
// speedup vs baseline: 1.0909x; 1.0909x over previous
#include <cuda_runtime.h>

#define NN 100000
#define NE 1600000
#define NG 256

// Scratch (static __device__ arrays; no allocation anywhere)
__device__ float g_bufA[NN * 64];
__device__ float g_bufB[NN * 64];
__device__ float g_tbuf[NN * 16];
__device__ float g_accum[NN * 32];
__device__ int   g_deg[NN];
__device__ int   g_pos[NN];
__device__ int   g_off[NN + 1];
__device__ int   g_csr[NE];
__device__ float g_pool[NG * 2];
__device__ float g_gcnt[NG];

// ---------------- CSR build ----------------

__global__ void k_zero_misc() {
    int i = blockIdx.x * blockDim.x + threadIdx.x;
    if (i < NN) { g_deg[i] = 0; g_pos[i] = 0; }
    if (i < NG * 2) g_pool[i] = 0.f;
    if (i < NG) g_gcnt[i] = 0.f;
}

__global__ void k_deg(const int* __restrict__ dst) {
    int e = blockIdx.x * blockDim.x + threadIdx.x;
    if (e < NE) atomicAdd(&g_deg[dst[e]], 1);
}

// single-block exclusive scan of g_deg -> g_off (1024 threads)
__global__ void __launch_bounds__(1024) k_scan() {
    __shared__ int ssum[1024];
    const int CH = (NN + 1023) / 1024;  // 98
    int t = threadIdx.x;
    int base = t * CH;
    int s = 0;
    for (int i = 0; i < CH; i++) {
        int idx = base + i;
        if (idx < NN) s += g_deg[idx];
    }
    ssum[t] = s;
    __syncthreads();
    // Hillis-Steele inclusive scan
    for (int o = 1; o < 1024; o <<= 1) {
        int v = (t >= o) ? ssum[t - o] : 0;
        __syncthreads();
        ssum[t] += v;
        __syncthreads();
    }
    int run = (t > 0) ? ssum[t - 1] : 0;
    for (int i = 0; i < CH; i++) {
        int idx = base + i;
        if (idx < NN) {
            g_off[idx] = run;
            run += g_deg[idx];
        }
    }
    if (t == 1023) g_off[NN] = run;
}

__global__ void k_fill(const int* __restrict__ src, const int* __restrict__ dst) {
    int e = blockIdx.x * blockDim.x + threadIdx.x;
    if (e >= NE) return;
    int d = dst[e];
    int p = g_off[d] + atomicAdd(&g_pos[d], 1);
    g_csr[p] = src[e];
}

// ---------------- dense node transforms ----------------

// t[i,:] = h[i,:] @ W  (DIN x DOUT)
template <int DIN, int DOUT>
__global__ void k_transform(const float* __restrict__ h,
                            const float* __restrict__ W,
                            float* __restrict__ t) {
    __shared__ float sW[DIN * DOUT];
    for (int idx = threadIdx.x; idx < DIN * DOUT; idx += blockDim.x) sW[idx] = W[idx];
    __syncthreads();
    int i = blockIdx.x * blockDim.x + threadIdx.x;
    if (i >= NN) return;
    float acc[DOUT];
#pragma unroll
    for (int j = 0; j < DOUT; j++) acc[j] = 0.f;
#pragma unroll 2
    for (int k = 0; k < DIN; k++) {
        float hv = h[(size_t)i * DIN + k];
#pragma unroll
        for (int j = 0; j < DOUT; j++) acc[j] += hv * sW[k * DOUT + j];
    }
#pragma unroll
    for (int j = 0; j < DOUT; j++) t[(size_t)i * DOUT + j] = acc[j];
}

// ---------------- warp-per-node CSR gather (no atomics) ----------------
// W must be a power of two (2, 16, 32). Lanes: channel = lane % W,
// edge-slot = lane / W; shfl-reduce across slots.
template <int W>
__global__ void k_gather(const float* __restrict__ t) {
    int gw = (blockIdx.x * blockDim.x + threadIdx.x) >> 5;
    if (gw >= NN) return;
    int lane = threadIdx.x & 31;
    constexpr int EPAR = 32 / W;
    int c = lane & (W - 1);
    int slot = lane >> __popc(W - 1);  // lane / W (W is pow2)
    int s0 = g_off[gw], s1 = g_off[gw + 1];
    float acc = 0.f;
    for (int e = s0 + slot; e < s1; e += EPAR) {
        int s = g_csr[e];
        acc += t[(size_t)s * W + c];
    }
#pragma unroll
    for (int m = W; m < 32; m <<= 1) acc += __shfl_xor_sync(0xffffffffu, acc, m);
    if (lane < W) g_accum[(size_t)gw * W + c] = acc;
}

// ---------------- layer update kernels ----------------

// post-transform: out = relu((accum/deg) @ Wl + bl + h @ Wr); accum width DIN
template <int DIN, int DOUT>
__global__ void k_update_post(const float* __restrict__ h,
                              const float* __restrict__ Wl,
                              const float* __restrict__ bl,
                              const float* __restrict__ Wr,
                              float* __restrict__ out) {
    __shared__ float sWl[DIN * DOUT];
    __shared__ float sWr[DIN * DOUT];
    __shared__ float sb[DOUT];
    for (int idx = threadIdx.x; idx < DIN * DOUT; idx += blockDim.x) {
        sWl[idx] = Wl[idx];
        sWr[idx] = Wr[idx];
    }
    for (int idx = threadIdx.x; idx < DOUT; idx += blockDim.x) sb[idx] = bl[idx];
    __syncthreads();
    int i = blockIdx.x * blockDim.x + threadIdx.x;
    if (i >= NN) return;
    float deg = (float)(g_off[i + 1] - g_off[i]);
    float inv = 1.f / fmaxf(deg, 1.f);
    float acc[DOUT];
#pragma unroll
    for (int j = 0; j < DOUT; j++) acc[j] = sb[j];
#pragma unroll 2
    for (int k = 0; k < DIN; k++) {
        float a = g_accum[(size_t)i * DIN + k] * inv;
        float hv = h[(size_t)i * DIN + k];
#pragma unroll
        for (int j = 0; j < DOUT; j++) {
            acc[j] += a * sWl[k * DOUT + j];
            acc[j] += hv * sWr[k * DOUT + j];
        }
    }
#pragma unroll
    for (int j = 0; j < DOUT; j++) out[(size_t)i * DOUT + j] = fmaxf(acc[j], 0.f);
}

// pre-transform: out = relu(accum/deg + bl + h @ Wr); accum width DOUT
template <int DIN, int DOUT>
__global__ void k_update_pre(const float* __restrict__ h,
                             const float* __restrict__ bl,
                             const float* __restrict__ Wr,
                             float* __restrict__ out) {
    __shared__ float sWr[DIN * DOUT];
    __shared__ float sb[DOUT];
    for (int idx = threadIdx.x; idx < DIN * DOUT; idx += blockDim.x) sWr[idx] = Wr[idx];
    for (int idx = threadIdx.x; idx < DOUT; idx += blockDim.x) sb[idx] = bl[idx];
    __syncthreads();
    int i = blockIdx.x * blockDim.x + threadIdx.x;
    if (i >= NN) return;
    float deg = (float)(g_off[i + 1] - g_off[i]);
    float inv = 1.f / fmaxf(deg, 1.f);
    float acc[DOUT];
#pragma unroll
    for (int j = 0; j < DOUT; j++) acc[j] = g_accum[(size_t)i * DOUT + j] * inv + sb[j];
#pragma unroll 2
    for (int k = 0; k < DIN; k++) {
        float hv = h[(size_t)i * DIN + k];
#pragma unroll
        for (int j = 0; j < DOUT; j++) acc[j] += hv * sWr[k * DOUT + j];
    }
#pragma unroll
    for (int j = 0; j < DOUT; j++) out[(size_t)i * DOUT + j] = fmaxf(acc[j], 0.f);
}

// ---------------- pooling + softmax ----------------

__global__ void k_pool(const float* __restrict__ h, const int* __restrict__ batch) {
    int i = blockIdx.x * blockDim.x + threadIdx.x;
    if (i >= NN) return;
    int g = batch[i];
    atomicAdd(&g_pool[2 * g + 0], h[(size_t)2 * i + 0]);
    atomicAdd(&g_pool[2 * g + 1], h[(size_t)2 * i + 1]);
    atomicAdd(&g_gcnt[g], 1.f);
}

__global__ void k_softmax(float* __restrict__ out) {
    int g = blockIdx.x * blockDim.x + threadIdx.x;
    if (g >= NG) return;
    float c = fmaxf(g_gcnt[g], 1.f);
    float a = g_pool[2 * g + 0] / c;
    float b = g_pool[2 * g + 1] / c;
    float m = fmaxf(a, b);
    float ea = expf(a - m);
    float eb = expf(b - m);
    float s = ea + eb;
    out[2 * g + 0] = ea / s;
    out[2 * g + 1] = eb / s;
}

extern "C" void kernel_launch(void* const* d_in, const int* in_sizes, int n_in,
                              void* d_out, int out_size) {
    const float* x = (const float*)d_in[0];
    const int* ei = (const int*)d_in[1];
    const int* batch = (const int*)d_in[2];
    const float* Wl0 = (const float*)d_in[3];
    const float* bl0 = (const float*)d_in[4];
    const float* Wr0 = (const float*)d_in[5];
    const float* Wl1 = (const float*)d_in[6];
    const float* bl1 = (const float*)d_in[7];
    const float* Wr1 = (const float*)d_in[8];
    const float* Wl2 = (const float*)d_in[9];
    const float* bl2 = (const float*)d_in[10];
    const float* Wr2 = (const float*)d_in[11];
    const float* Wl3 = (const float*)d_in[12];
    const float* bl3 = (const float*)d_in[13];
    const float* Wr3 = (const float*)d_in[14];
    float* out = (float*)d_out;

    const int* src = ei;
    const int* dst = ei + NE;

    float *bufA, *bufB, *tbuf;
    cudaGetSymbolAddress((void**)&bufA, g_bufA);
    cudaGetSymbolAddress((void**)&bufB, g_bufB);
    cudaGetSymbolAddress((void**)&tbuf, g_tbuf);

    const int TB = 256;
    auto nb = [](long n, int tb) { return (int)((n + tb - 1) / tb); };
    const int GATHER_GRID = nb((long)NN * 32, TB);  // warp per node

    // CSR build (per launch; deterministic work)
    k_zero_misc<<<nb(NN, TB), TB>>>();
    k_deg<<<nb(NE, TB), TB>>>(dst);
    k_scan<<<1, 1024>>>();
    k_fill<<<nb(NE, TB), TB>>>(src, dst);

    // L0: 56 -> 16 (pre-transform, gather width 16)
    k_transform<56, 16><<<nb(NN, 128), 128>>>(x, Wl0, tbuf);
    k_gather<16><<<GATHER_GRID, TB>>>(tbuf);
    k_update_pre<56, 16><<<nb(NN, 128), 128>>>(x, bl0, Wr0, bufA);

    // L1: 16 -> 32 (post-transform, gather width 16)
    k_gather<16><<<GATHER_GRID, TB>>>(bufA);
    k_update_post<16, 32><<<nb(NN, 128), 128>>>(bufA, Wl1, bl1, Wr1, bufB);

    // L2: 32 -> 64 (post-transform, gather width 32)
    k_gather<32><<<GATHER_GRID, TB>>>(bufB);
    k_update_post<32, 64><<<nb(NN, 128), 128>>>(bufB, Wl2, bl2, Wr2, bufA);

    // L3: 64 -> 2 (pre-transform, gather width 2)
    k_transform<64, 2><<<nb(NN, 128), 128>>>(bufA, Wl3, tbuf);
    k_gather<2><<<GATHER_GRID, TB>>>(tbuf);
    k_update_pre<64, 2><<<nb(NN, 128), 128>>>(bufA, bl3, Wr3, bufB);

    // global mean pool + softmax
    k_pool<<<nb(NN, TB), TB>>>(bufB, batch);
    k_softmax<<<1, 256>>>(out);
}

// round 7
// speedup vs baseline: 1.3570x; 1.2439x over previous
#include <cuda_runtime.h>

#define NN 100000
#define NE 1600000
#define NG 256
#define SCAN_NB ((NN + 255) / 256)   // 391

// Scratch (static __device__ arrays; no allocation anywhere)
__device__ float g_bufA[NN * 64];
__device__ float g_bufB[NN * 64];
__device__ float g_tbuf[NN * 16];
__device__ float g_accum[NN * 32];
__device__ int   g_deg[NN];
__device__ int   g_pos[NN];
__device__ int   g_off[NN + 1];
__device__ int   g_bsum[SCAN_NB];
__device__ int   g_boff[SCAN_NB];
__device__ int   g_csr[NE];
__device__ float g_pool[NG * 2];
__device__ float g_gcnt[NG];

// ---------------- CSR build ----------------

__global__ void k_zero_misc() {
    int i = blockIdx.x * blockDim.x + threadIdx.x;
    if (i < NN) { g_deg[i] = 0; g_pos[i] = 0; }
    if (i < NG * 2) g_pool[i] = 0.f;
    if (i < NG) g_gcnt[i] = 0.f;
}

__global__ void k_deg(const int* __restrict__ dst) {
    int e = blockIdx.x * blockDim.x + threadIdx.x;
    if (e < NE) atomicAdd(&g_deg[dst[e]], 1);
}

// scan stage 1: per-block (256-elem) sums
__global__ void k_scan1() {
    __shared__ int sh[256];
    int t = threadIdx.x;
    int i = blockIdx.x * 256 + t;
    sh[t] = (i < NN) ? g_deg[i] : 0;
    __syncthreads();
    for (int o = 128; o > 0; o >>= 1) {
        if (t < o) sh[t] += sh[t + o];
        __syncthreads();
    }
    if (t == 0) g_bsum[blockIdx.x] = sh[0];
}

// scan stage 2: single block scans SCAN_NB block sums -> exclusive g_boff
__global__ void __launch_bounds__(512) k_scan2() {
    __shared__ int sh[512];
    int t = threadIdx.x;
    sh[t] = (t < SCAN_NB) ? g_bsum[t] : 0;
    __syncthreads();
    for (int o = 1; o < 512; o <<= 1) {
        int v = (t >= o) ? sh[t - o] : 0;
        __syncthreads();
        sh[t] += v;
        __syncthreads();
    }
    if (t < SCAN_NB) g_boff[t] = sh[t] - g_bsum[t];  // exclusive
}

// scan stage 3: per-block inner exclusive scan + block offset -> g_off
__global__ void k_scan3() {
    __shared__ int sh[256];
    int t = threadIdx.x;
    int i = blockIdx.x * 256 + t;
    int v = (i < NN) ? g_deg[i] : 0;
    sh[t] = v;
    __syncthreads();
    for (int o = 1; o < 256; o <<= 1) {
        int u = (t >= o) ? sh[t - o] : 0;
        __syncthreads();
        sh[t] += u;
        __syncthreads();
    }
    if (i < NN) g_off[i] = g_boff[blockIdx.x] + sh[t] - v;
    if (i == NN - 1) g_off[NN] = NE;  // total degree == NE by construction
}

__global__ void k_fill(const int* __restrict__ src, const int* __restrict__ dst) {
    int e = blockIdx.x * blockDim.x + threadIdx.x;
    if (e >= NE) return;
    int d = dst[e];
    int p = g_off[d] + atomicAdd(&g_pos[d], 1);
    g_csr[p] = src[e];
}

// ---------------- dense node transforms ----------------

template <int DIN, int DOUT>
__global__ void k_transform(const float* __restrict__ h,
                            const float* __restrict__ W,
                            float* __restrict__ t) {
    __shared__ float sW[DIN * DOUT];
    for (int idx = threadIdx.x; idx < DIN * DOUT; idx += blockDim.x) sW[idx] = W[idx];
    __syncthreads();
    int i = blockIdx.x * blockDim.x + threadIdx.x;
    if (i >= NN) return;
    float acc[DOUT];
#pragma unroll
    for (int j = 0; j < DOUT; j++) acc[j] = 0.f;
#pragma unroll 2
    for (int k = 0; k < DIN; k++) {
        float hv = h[(size_t)i * DIN + k];
#pragma unroll
        for (int j = 0; j < DOUT; j++) acc[j] += hv * sW[k * DOUT + j];
    }
#pragma unroll
    for (int j = 0; j < DOUT; j++) t[(size_t)i * DOUT + j] = acc[j];
}

// ---------------- warp-per-node CSR gathers (no atomics, high MLP) ----------------
// Pattern: coalesced load of up to 32 CSR indices per warp chunk, then a
// UNIFORM-trip-count broadcast loop (all lanes execute every shfl; the
// feature load/accumulate is predicated). 4-8 independent float4 loads in
// flight per chunk -> MLP >= 4.

// W=16: lane = (slot:3 | c4:2), 8 edge slots, float4 per lane
__global__ void k_gather16(const float* __restrict__ t) {
    int gw = (blockIdx.x * blockDim.x + threadIdx.x) >> 5;
    if (gw >= NN) return;
    int lane = threadIdx.x & 31;
    int c4 = lane & 3;
    int slot = lane >> 2;
    int s0 = g_off[gw];
    int deg = g_off[gw + 1] - s0;
    float4 acc = make_float4(0.f, 0.f, 0.f, 0.f);
    for (int base = 0; base < deg; base += 32) {
        int idx = base + lane;
        int si = (idx < deg) ? g_csr[s0 + idx] : 0;
        int lim = deg - base;
#pragma unroll
        for (int jb = 0; jb < 32; jb += 8) {
            int j = jb + slot;                         // uniform trip count: 4
            int s = __shfl_sync(0xffffffffu, si, j);   // convergent
            if (j < lim) {
                float4 v = *reinterpret_cast<const float4*>(t + (size_t)s * 16 + c4 * 4);
                acc.x += v.x; acc.y += v.y; acc.z += v.z; acc.w += v.w;
            }
        }
    }
#pragma unroll
    for (int m = 4; m < 32; m <<= 1) {
        acc.x += __shfl_xor_sync(0xffffffffu, acc.x, m);
        acc.y += __shfl_xor_sync(0xffffffffu, acc.y, m);
        acc.z += __shfl_xor_sync(0xffffffffu, acc.z, m);
        acc.w += __shfl_xor_sync(0xffffffffu, acc.w, m);
    }
    if (lane < 4)
        *reinterpret_cast<float4*>(g_accum + (size_t)gw * 16 + c4 * 4) = acc;
}

// W=32: lane = (slot:2 | c4:3), 4 edge slots, float4 per lane
__global__ void k_gather32(const float* __restrict__ t) {
    int gw = (blockIdx.x * blockDim.x + threadIdx.x) >> 5;
    if (gw >= NN) return;
    int lane = threadIdx.x & 31;
    int c4 = lane & 7;
    int slot = lane >> 3;
    int s0 = g_off[gw];
    int deg = g_off[gw + 1] - s0;
    float4 acc = make_float4(0.f, 0.f, 0.f, 0.f);
    for (int base = 0; base < deg; base += 32) {
        int idx = base + lane;
        int si = (idx < deg) ? g_csr[s0 + idx] : 0;
        int lim = deg - base;
#pragma unroll
        for (int jb = 0; jb < 32; jb += 4) {
            int j = jb + slot;                         // uniform trip count: 8
            int s = __shfl_sync(0xffffffffu, si, j);   // convergent
            if (j < lim) {
                float4 v = *reinterpret_cast<const float4*>(t + (size_t)s * 32 + c4 * 4);
                acc.x += v.x; acc.y += v.y; acc.z += v.z; acc.w += v.w;
            }
        }
    }
#pragma unroll
    for (int m = 8; m < 32; m <<= 1) {
        acc.x += __shfl_xor_sync(0xffffffffu, acc.x, m);
        acc.y += __shfl_xor_sync(0xffffffffu, acc.y, m);
        acc.z += __shfl_xor_sync(0xffffffffu, acc.z, m);
        acc.w += __shfl_xor_sync(0xffffffffu, acc.w, m);
    }
    if (lane < 8)
        *reinterpret_cast<float4*>(g_accum + (size_t)gw * 32 + c4 * 4) = acc;
}

// W=2: each lane owns whole edges (float2), 32 edge slots
__global__ void k_gather2(const float* __restrict__ t) {
    int gw = (blockIdx.x * blockDim.x + threadIdx.x) >> 5;
    if (gw >= NN) return;
    int lane = threadIdx.x & 31;
    int s0 = g_off[gw], s1 = g_off[gw + 1];
    float ax = 0.f, ay = 0.f;
    for (int e = s0 + lane; e < s1; e += 32) {
        int s = g_csr[e];
        float2 v = *reinterpret_cast<const float2*>(t + (size_t)s * 2);
        ax += v.x; ay += v.y;
    }
#pragma unroll
    for (int m = 1; m < 32; m <<= 1) {
        ax += __shfl_xor_sync(0xffffffffu, ax, m);
        ay += __shfl_xor_sync(0xffffffffu, ay, m);
    }
    if (lane == 0)
        *reinterpret_cast<float2*>(g_accum + (size_t)gw * 2) = make_float2(ax, ay);
}

// ---------------- layer update kernels ----------------

template <int DIN, int DOUT>
__global__ void k_update_post(const float* __restrict__ h,
                              const float* __restrict__ Wl,
                              const float* __restrict__ bl,
                              const float* __restrict__ Wr,
                              float* __restrict__ out) {
    __shared__ float sWl[DIN * DOUT];
    __shared__ float sWr[DIN * DOUT];
    __shared__ float sb[DOUT];
    for (int idx = threadIdx.x; idx < DIN * DOUT; idx += blockDim.x) {
        sWl[idx] = Wl[idx];
        sWr[idx] = Wr[idx];
    }
    for (int idx = threadIdx.x; idx < DOUT; idx += blockDim.x) sb[idx] = bl[idx];
    __syncthreads();
    int i = blockIdx.x * blockDim.x + threadIdx.x;
    if (i >= NN) return;
    float deg = (float)(g_off[i + 1] - g_off[i]);
    float inv = 1.f / fmaxf(deg, 1.f);
    float acc[DOUT];
#pragma unroll
    for (int j = 0; j < DOUT; j++) acc[j] = sb[j];
#pragma unroll 2
    for (int k = 0; k < DIN; k++) {
        float a = g_accum[(size_t)i * DIN + k] * inv;
        float hv = h[(size_t)i * DIN + k];
#pragma unroll
        for (int j = 0; j < DOUT; j++) {
            acc[j] += a * sWl[k * DOUT + j];
            acc[j] += hv * sWr[k * DOUT + j];
        }
    }
#pragma unroll
    for (int j = 0; j < DOUT; j++) out[(size_t)i * DOUT + j] = fmaxf(acc[j], 0.f);
}

template <int DIN, int DOUT>
__global__ void k_update_pre(const float* __restrict__ h,
                             const float* __restrict__ bl,
                             const float* __restrict__ Wr,
                             float* __restrict__ out) {
    __shared__ float sWr[DIN * DOUT];
    __shared__ float sb[DOUT];
    for (int idx = threadIdx.x; idx < DIN * DOUT; idx += blockDim.x) sWr[idx] = Wr[idx];
    for (int idx = threadIdx.x; idx < DOUT; idx += blockDim.x) sb[idx] = bl[idx];
    __syncthreads();
    int i = blockIdx.x * blockDim.x + threadIdx.x;
    if (i >= NN) return;
    float deg = (float)(g_off[i + 1] - g_off[i]);
    float inv = 1.f / fmaxf(deg, 1.f);
    float acc[DOUT];
#pragma unroll
    for (int j = 0; j < DOUT; j++) acc[j] = g_accum[(size_t)i * DOUT + j] * inv + sb[j];
#pragma unroll 2
    for (int k = 0; k < DIN; k++) {
        float hv = h[(size_t)i * DIN + k];
#pragma unroll
        for (int j = 0; j < DOUT; j++) acc[j] += hv * sWr[k * DOUT + j];
    }
#pragma unroll
    for (int j = 0; j < DOUT; j++) out[(size_t)i * DOUT + j] = fmaxf(acc[j], 0.f);
}

// ---------------- pooling + softmax ----------------

__global__ void k_pool(const float* __restrict__ h, const int* __restrict__ batch) {
    int i = blockIdx.x * blockDim.x + threadIdx.x;
    if (i >= NN) return;
    int g = batch[i];
    atomicAdd(&g_pool[2 * g + 0], h[(size_t)2 * i + 0]);
    atomicAdd(&g_pool[2 * g + 1], h[(size_t)2 * i + 1]);
    atomicAdd(&g_gcnt[g], 1.f);
}

__global__ void k_softmax(float* __restrict__ out) {
    int g = blockIdx.x * blockDim.x + threadIdx.x;
    if (g >= NG) return;
    float c = fmaxf(g_gcnt[g], 1.f);
    float a = g_pool[2 * g + 0] / c;
    float b = g_pool[2 * g + 1] / c;
    float m = fmaxf(a, b);
    float ea = expf(a - m);
    float eb = expf(b - m);
    float s = ea + eb;
    out[2 * g + 0] = ea / s;
    out[2 * g + 1] = eb / s;
}

extern "C" void kernel_launch(void* const* d_in, const int* in_sizes, int n_in,
                              void* d_out, int out_size) {
    const float* x = (const float*)d_in[0];
    const int* ei = (const int*)d_in[1];
    const int* batch = (const int*)d_in[2];
    const float* Wl0 = (const float*)d_in[3];
    const float* bl0 = (const float*)d_in[4];
    const float* Wr0 = (const float*)d_in[5];
    const float* Wl1 = (const float*)d_in[6];
    const float* bl1 = (const float*)d_in[7];
    const float* Wr1 = (const float*)d_in[8];
    const float* Wl2 = (const float*)d_in[9];
    const float* bl2 = (const float*)d_in[10];
    const float* Wr2 = (const float*)d_in[11];
    const float* Wl3 = (const float*)d_in[12];
    const float* bl3 = (const float*)d_in[13];
    const float* Wr3 = (const float*)d_in[14];
    float* out = (float*)d_out;

    const int* src = ei;
    const int* dst = ei + NE;

    float *bufA, *bufB, *tbuf;
    cudaGetSymbolAddress((void**)&bufA, g_bufA);
    cudaGetSymbolAddress((void**)&bufB, g_bufB);
    cudaGetSymbolAddress((void**)&tbuf, g_tbuf);

    const int TB = 256;
    auto nb = [](long n, int tb) { return (int)((n + tb - 1) / tb); };
    const int GATHER_GRID = nb((long)NN * 32, TB);  // warp per node

    // CSR build (per launch; deterministic work)
    k_zero_misc<<<nb(NN, TB), TB>>>();
    k_deg<<<nb(NE, TB), TB>>>(dst);
    k_scan1<<<SCAN_NB, 256>>>();
    k_scan2<<<1, 512>>>();
    k_scan3<<<SCAN_NB, 256>>>();
    k_fill<<<nb(NE, TB), TB>>>(src, dst);

    // L0: 56 -> 16 (pre-transform, gather width 16)
    k_transform<56, 16><<<nb(NN, 128), 128>>>(x, Wl0, tbuf);
    k_gather16<<<GATHER_GRID, TB>>>(tbuf);
    k_update_pre<56, 16><<<nb(NN, 128), 128>>>(x, bl0, Wr0, bufA);

    // L1: 16 -> 32 (post-transform, gather width 16)
    k_gather16<<<GATHER_GRID, TB>>>(bufA);
    k_update_post<16, 32><<<nb(NN, 128), 128>>>(bufA, Wl1, bl1, Wr1, bufB);

    // L2: 32 -> 64 (post-transform, gather width 32)
    k_gather32<<<GATHER_GRID, TB>>>(bufB);
    k_update_post<32, 64><<<nb(NN, 128), 128>>>(bufB, Wl2, bl2, Wr2, bufA);

    // L3: 64 -> 2 (pre-transform, gather width 2)
    k_transform<64, 2><<<nb(NN, 128), 128>>>(bufA, Wl3, tbuf);
    k_gather2<<<GATHER_GRID, TB>>>(tbuf);
    k_update_pre<64, 2><<<nb(NN, 128), 128>>>(bufA, bl3, Wr3, bufB);

    // global mean pool + softmax
    k_pool<<<nb(NN, TB), TB>>>(bufB, batch);
    k_softmax<<<1, 256>>>(out);
}

// round 8
// speedup vs baseline: 1.3931x; 1.0266x over previous
#include <cuda_runtime.h>

#define NN 100000
#define NE 1600000
#define NG 256
#define SCAN_NB ((NN + 255) / 256)   // 391

// Scratch (static __device__ arrays; no allocation anywhere)
__device__ float g_bufA[NN * 64];
__device__ float g_bufB[NN * 64];
__device__ float g_tbuf[NN * 16];   // scatter operand (<=16 wide)
__device__ float g_rbuf[NN * 16];   // right-path r = h@Wr + b (<=16 wide)
__device__ int   g_deg[NN];
__device__ int   g_pos[NN];
__device__ int   g_off[NN + 1];
__device__ int   g_bsum[SCAN_NB];
__device__ int   g_boff[SCAN_NB];
__device__ int   g_csr[NE];
__device__ float g_pool[NG * 2];
__device__ float g_gcnt[NG];

// ---------------- CSR build ----------------

__global__ void k_zero_misc() {
    int i = blockIdx.x * blockDim.x + threadIdx.x;
    if (i < NN) { g_deg[i] = 0; g_pos[i] = 0; }
    if (i < NG * 2) g_pool[i] = 0.f;
    if (i < NG) g_gcnt[i] = 0.f;
}

__global__ void k_deg(const int* __restrict__ dst) {
    int e = blockIdx.x * blockDim.x + threadIdx.x;
    if (e < NE) atomicAdd(&g_deg[dst[e]], 1);
}

__global__ void k_scan1() {
    __shared__ int sh[256];
    int t = threadIdx.x;
    int i = blockIdx.x * 256 + t;
    sh[t] = (i < NN) ? g_deg[i] : 0;
    __syncthreads();
    for (int o = 128; o > 0; o >>= 1) {
        if (t < o) sh[t] += sh[t + o];
        __syncthreads();
    }
    if (t == 0) g_bsum[blockIdx.x] = sh[0];
}

__global__ void __launch_bounds__(512) k_scan2() {
    __shared__ int sh[512];
    int t = threadIdx.x;
    sh[t] = (t < SCAN_NB) ? g_bsum[t] : 0;
    __syncthreads();
    for (int o = 1; o < 512; o <<= 1) {
        int v = (t >= o) ? sh[t - o] : 0;
        __syncthreads();
        sh[t] += v;
        __syncthreads();
    }
    if (t < SCAN_NB) g_boff[t] = sh[t] - g_bsum[t];  // exclusive
}

__global__ void k_scan3() {
    __shared__ int sh[256];
    int t = threadIdx.x;
    int i = blockIdx.x * 256 + t;
    int v = (i < NN) ? g_deg[i] : 0;
    sh[t] = v;
    __syncthreads();
    for (int o = 1; o < 256; o <<= 1) {
        int u = (t >= o) ? sh[t - o] : 0;
        __syncthreads();
        sh[t] += u;
        __syncthreads();
    }
    if (i < NN) g_off[i] = g_boff[blockIdx.x] + sh[t] - v;
    if (i == NN - 1) g_off[NN] = NE;
}

__global__ void k_fill(const int* __restrict__ src, const int* __restrict__ dst) {
    int e = blockIdx.x * blockDim.x + threadIdx.x;
    if (e >= NE) return;
    int d = dst[e];
    int p = g_off[d] + atomicAdd(&g_pos[d], 1);
    g_csr[p] = src[e];
}

// ---------------- prep kernels (one read of h, two outputs) ----------------

// tbuf = h@Wl (DOUT wide), rbuf = h@Wr + b (DOUT wide)
template <int DIN, int DOUT>
__global__ void k_prep(const float* __restrict__ h,
                       const float* __restrict__ Wl,
                       const float* __restrict__ bl,
                       const float* __restrict__ Wr,
                       float* __restrict__ t,
                       float* __restrict__ r) {
    __shared__ float sWl[DIN * DOUT];
    __shared__ float sWr[DIN * DOUT];
    __shared__ float sb[DOUT];
    for (int idx = threadIdx.x; idx < DIN * DOUT; idx += blockDim.x) {
        sWl[idx] = Wl[idx];
        sWr[idx] = Wr[idx];
    }
    for (int idx = threadIdx.x; idx < DOUT; idx += blockDim.x) sb[idx] = bl[idx];
    __syncthreads();
    int i = blockIdx.x * blockDim.x + threadIdx.x;
    if (i >= NN) return;
    float al[DOUT], ar[DOUT];
#pragma unroll
    for (int j = 0; j < DOUT; j++) { al[j] = 0.f; ar[j] = sb[j]; }
#pragma unroll 2
    for (int k = 0; k < DIN; k++) {
        float hv = h[(size_t)i * DIN + k];
#pragma unroll
        for (int j = 0; j < DOUT; j++) {
            al[j] += hv * sWl[k * DOUT + j];
            ar[j] += hv * sWr[k * DOUT + j];
        }
    }
#pragma unroll
    for (int j = 0; j < DOUT; j++) {
        t[(size_t)i * DOUT + j] = al[j];
        r[(size_t)i * DOUT + j] = ar[j];
    }
}

// ---------------- fused gather kernels (warp per node, no atomics) ----------------

// L0 (pre, W=16): out = relu(agg/deg + r)
__global__ void k_gather16_pre(const float* __restrict__ t,
                               const float* __restrict__ r,
                               float* __restrict__ out) {
    int gw = (blockIdx.x * blockDim.x + threadIdx.x) >> 5;
    if (gw >= NN) return;
    int lane = threadIdx.x & 31;
    int c4 = lane & 3;
    int slot = lane >> 2;
    int s0 = g_off[gw];
    int deg = g_off[gw + 1] - s0;
    float4 acc = make_float4(0.f, 0.f, 0.f, 0.f);
    for (int base = 0; base < deg; base += 32) {
        int idx = base + lane;
        int si = (idx < deg) ? g_csr[s0 + idx] : 0;
        int lim = deg - base;
#pragma unroll
        for (int jb = 0; jb < 32; jb += 8) {
            int j = jb + slot;
            int s = __shfl_sync(0xffffffffu, si, j);
            if (j < lim) {
                float4 v = *reinterpret_cast<const float4*>(t + (size_t)s * 16 + c4 * 4);
                acc.x += v.x; acc.y += v.y; acc.z += v.z; acc.w += v.w;
            }
        }
    }
#pragma unroll
    for (int m = 4; m < 32; m <<= 1) {
        acc.x += __shfl_xor_sync(0xffffffffu, acc.x, m);
        acc.y += __shfl_xor_sync(0xffffffffu, acc.y, m);
        acc.z += __shfl_xor_sync(0xffffffffu, acc.z, m);
        acc.w += __shfl_xor_sync(0xffffffffu, acc.w, m);
    }
    float inv = 1.f / fmaxf((float)deg, 1.f);
    if (lane < 4) {
        float4 rv = *reinterpret_cast<const float4*>(r + (size_t)gw * 16 + c4 * 4);
        float4 o;
        o.x = fmaxf(acc.x * inv + rv.x, 0.f);
        o.y = fmaxf(acc.y * inv + rv.y, 0.f);
        o.z = fmaxf(acc.z * inv + rv.z, 0.f);
        o.w = fmaxf(acc.w * inv + rv.w, 0.f);
        *reinterpret_cast<float4*>(out + (size_t)gw * 16 + c4 * 4) = o;
    }
}

// L1 (post, 16->32): out = relu((agg/deg)@Wl + b + h@Wr), fully in-warp
__global__ void __launch_bounds__(256) k_gather16_post(
        const float* __restrict__ h,
        const float* __restrict__ Wl,
        const float* __restrict__ bl,
        const float* __restrict__ Wr,
        float* __restrict__ out) {
    __shared__ float sWl[16 * 32];
    __shared__ float sWr[16 * 32];
    __shared__ float sb[32];
    for (int idx = threadIdx.x; idx < 16 * 32; idx += blockDim.x) {
        sWl[idx] = Wl[idx];
        sWr[idx] = Wr[idx];
    }
    if (threadIdx.x < 32) sb[threadIdx.x] = bl[threadIdx.x];
    __syncthreads();
    int gw = (blockIdx.x * blockDim.x + threadIdx.x) >> 5;
    if (gw >= NN) return;
    int lane = threadIdx.x & 31;
    int c4 = lane & 3;
    int slot = lane >> 2;
    int s0 = g_off[gw];
    int deg = g_off[gw + 1] - s0;
    float4 acc = make_float4(0.f, 0.f, 0.f, 0.f);
    for (int base = 0; base < deg; base += 32) {
        int idx = base + lane;
        int si = (idx < deg) ? g_csr[s0 + idx] : 0;
        int lim = deg - base;
#pragma unroll
        for (int jb = 0; jb < 32; jb += 8) {
            int j = jb + slot;
            int s = __shfl_sync(0xffffffffu, si, j);
            if (j < lim) {
                float4 v = *reinterpret_cast<const float4*>(h + (size_t)s * 16 + c4 * 4);
                acc.x += v.x; acc.y += v.y; acc.z += v.z; acc.w += v.w;
            }
        }
    }
#pragma unroll
    for (int m = 4; m < 32; m <<= 1) {
        acc.x += __shfl_xor_sync(0xffffffffu, acc.x, m);
        acc.y += __shfl_xor_sync(0xffffffffu, acc.y, m);
        acc.z += __shfl_xor_sync(0xffffffffu, acc.z, m);
        acc.w += __shfl_xor_sync(0xffffffffu, acc.w, m);
    }
    float inv = 1.f / fmaxf((float)deg, 1.f);
    // own h-row element for broadcast (16 values in lanes 0..15)
    float hv_mine = (lane < 16) ? h[(size_t)gw * 16 + lane] : 0.f;
    float o = sb[lane];
    float accv[4] = {acc.x, acc.y, acc.z, acc.w};
#pragma unroll
    for (int k = 0; k < 16; k++) {
        float aggk = __shfl_sync(0xffffffffu, accv[k & 3], k >> 2) * inv;
        float hk = __shfl_sync(0xffffffffu, hv_mine, k);
        o += aggk * sWl[k * 32 + lane] + hk * sWr[k * 32 + lane];
    }
    out[(size_t)gw * 32 + lane] = fmaxf(o, 0.f);
}

// L2 (post, 32->64): out = relu((agg/deg)@Wl + b + h@Wr), 2 channels/lane
__global__ void __launch_bounds__(256) k_gather32_post(
        const float* __restrict__ h,
        const float* __restrict__ Wl,
        const float* __restrict__ bl,
        const float* __restrict__ Wr,
        float* __restrict__ out) {
    __shared__ float sWl[32 * 64];
    __shared__ float sWr[32 * 64];
    __shared__ float sb[64];
    for (int idx = threadIdx.x; idx < 32 * 64; idx += blockDim.x) {
        sWl[idx] = Wl[idx];
        sWr[idx] = Wr[idx];
    }
    if (threadIdx.x < 64) sb[threadIdx.x] = bl[threadIdx.x];
    __syncthreads();
    int gw = (blockIdx.x * blockDim.x + threadIdx.x) >> 5;
    if (gw >= NN) return;
    int lane = threadIdx.x & 31;
    int c4 = lane & 7;
    int slot = lane >> 3;
    int s0 = g_off[gw];
    int deg = g_off[gw + 1] - s0;
    float4 acc = make_float4(0.f, 0.f, 0.f, 0.f);
    for (int base = 0; base < deg; base += 32) {
        int idx = base + lane;
        int si = (idx < deg) ? g_csr[s0 + idx] : 0;
        int lim = deg - base;
#pragma unroll
        for (int jb = 0; jb < 32; jb += 4) {
            int j = jb + slot;
            int s = __shfl_sync(0xffffffffu, si, j);
            if (j < lim) {
                float4 v = *reinterpret_cast<const float4*>(h + (size_t)s * 32 + c4 * 4);
                acc.x += v.x; acc.y += v.y; acc.z += v.z; acc.w += v.w;
            }
        }
    }
#pragma unroll
    for (int m = 8; m < 32; m <<= 1) {
        acc.x += __shfl_xor_sync(0xffffffffu, acc.x, m);
        acc.y += __shfl_xor_sync(0xffffffffu, acc.y, m);
        acc.z += __shfl_xor_sync(0xffffffffu, acc.z, m);
        acc.w += __shfl_xor_sync(0xffffffffu, acc.w, m);
    }
    float inv = 1.f / fmaxf((float)deg, 1.f);
    float hv_mine = h[(size_t)gw * 32 + lane];   // 32 values across 32 lanes
    float o0 = sb[lane], o1 = sb[lane + 32];
    float accv[4] = {acc.x, acc.y, acc.z, acc.w};
#pragma unroll
    for (int k = 0; k < 32; k++) {
        float aggk = __shfl_sync(0xffffffffu, accv[k & 3], k >> 2) * inv;
        float hk = __shfl_sync(0xffffffffu, hv_mine, k);
        o0 += aggk * sWl[k * 64 + lane] + hk * sWr[k * 64 + lane];
        o1 += aggk * sWl[k * 64 + lane + 32] + hk * sWr[k * 64 + lane + 32];
    }
    out[(size_t)gw * 64 + lane] = fmaxf(o0, 0.f);
    out[(size_t)gw * 64 + lane + 32] = fmaxf(o1, 0.f);
}

// L3 (pre, W=2) + pooling fused: hfinal = relu(agg/deg + r); atomic pool
__global__ void k_gather2_pool(const float* __restrict__ t,
                               const float* __restrict__ r,
                               const int* __restrict__ batch) {
    int gw = (blockIdx.x * blockDim.x + threadIdx.x) >> 5;
    if (gw >= NN) return;
    int lane = threadIdx.x & 31;
    int s0 = g_off[gw], s1 = g_off[gw + 1];
    float ax = 0.f, ay = 0.f;
    for (int e = s0 + lane; e < s1; e += 32) {
        int s = g_csr[e];
        float2 v = *reinterpret_cast<const float2*>(t + (size_t)s * 2);
        ax += v.x; ay += v.y;
    }
#pragma unroll
    for (int m = 1; m < 32; m <<= 1) {
        ax += __shfl_xor_sync(0xffffffffu, ax, m);
        ay += __shfl_xor_sync(0xffffffffu, ay, m);
    }
    if (lane == 0) {
        float inv = 1.f / fmaxf((float)(s1 - s0), 1.f);
        float2 rv = *reinterpret_cast<const float2*>(r + (size_t)gw * 2);
        float hx = fmaxf(ax * inv + rv.x, 0.f);
        float hy = fmaxf(ay * inv + rv.y, 0.f);
        int g = batch[gw];
        atomicAdd(&g_pool[2 * g + 0], hx);
        atomicAdd(&g_pool[2 * g + 1], hy);
        atomicAdd(&g_gcnt[g], 1.f);
    }
}

__global__ void k_softmax(float* __restrict__ out) {
    int g = blockIdx.x * blockDim.x + threadIdx.x;
    if (g >= NG) return;
    float c = fmaxf(g_gcnt[g], 1.f);
    float a = g_pool[2 * g + 0] / c;
    float b = g_pool[2 * g + 1] / c;
    float m = fmaxf(a, b);
    float ea = expf(a - m);
    float eb = expf(b - m);
    float s = ea + eb;
    out[2 * g + 0] = ea / s;
    out[2 * g + 1] = eb / s;
}

extern "C" void kernel_launch(void* const* d_in, const int* in_sizes, int n_in,
                              void* d_out, int out_size) {
    const float* x = (const float*)d_in[0];
    const int* ei = (const int*)d_in[1];
    const int* batch = (const int*)d_in[2];
    const float* Wl0 = (const float*)d_in[3];
    const float* bl0 = (const float*)d_in[4];
    const float* Wr0 = (const float*)d_in[5];
    const float* Wl1 = (const float*)d_in[6];
    const float* bl1 = (const float*)d_in[7];
    const float* Wr1 = (const float*)d_in[8];
    const float* Wl2 = (const float*)d_in[9];
    const float* bl2 = (const float*)d_in[10];
    const float* Wr2 = (const float*)d_in[11];
    const float* Wl3 = (const float*)d_in[12];
    const float* bl3 = (const float*)d_in[13];
    const float* Wr3 = (const float*)d_in[14];
    float* out = (float*)d_out;

    const int* src = ei;
    const int* dst = ei + NE;

    float *bufA, *bufB, *tbuf, *rbuf;
    cudaGetSymbolAddress((void**)&bufA, g_bufA);
    cudaGetSymbolAddress((void**)&bufB, g_bufB);
    cudaGetSymbolAddress((void**)&tbuf, g_tbuf);
    cudaGetSymbolAddress((void**)&rbuf, g_rbuf);

    const int TB = 256;
    auto nb = [](long n, int tb) { return (int)((n + tb - 1) / tb); };
    const int GATHER_GRID = nb((long)NN * 32, TB);  // warp per node

    // CSR build (per launch; deterministic work)
    k_zero_misc<<<nb(NN, TB), TB>>>();
    k_deg<<<nb(NE, TB), TB>>>(dst);
    k_scan1<<<SCAN_NB, 256>>>();
    k_scan2<<<1, 512>>>();
    k_scan3<<<SCAN_NB, 256>>>();
    k_fill<<<nb(NE, TB), TB>>>(src, dst);

    // L0: 56 -> 16 (pre): prep (x read once) + fused gather epilogue
    k_prep<56, 16><<<nb(NN, 128), 128>>>(x, Wl0, bl0, Wr0, tbuf, rbuf);
    k_gather16_pre<<<GATHER_GRID, TB>>>(tbuf, rbuf, bufA);

    // L1: 16 -> 32 (post): fully fused gather + update
    k_gather16_post<<<GATHER_GRID, TB>>>(bufA, Wl1, bl1, Wr1, bufB);

    // L2: 32 -> 64 (post): fully fused gather + update
    k_gather32_post<<<GATHER_GRID, TB>>>(bufB, Wl2, bl2, Wr2, bufA);

    // L3: 64 -> 2 (pre): prep (bufA read once) + fused gather + pooling
    k_prep<64, 2><<<nb(NN, 128), 128>>>(bufA, Wl3, bl3, Wr3, tbuf, rbuf);
    k_gather2_pool<<<GATHER_GRID, TB>>>(tbuf, rbuf, batch);

    k_softmax<<<1, 256>>>(out);
}